// round 1
// baseline (speedup 1.0000x reference)
#include <cuda_runtime.h>
#include <cuda_bf16.h>
#include <mma.h>
#include <math.h>

using namespace nvcuda;

// Problem constants
#define B_   4
#define T_   4096
#define C_   1024
#define H_   4096
#define E_   8
#define CAP  1024   // int(2.0 * T / E)

// ---------------- device scratch (no allocations allowed) ----------------
__device__ float  g_probs[B_ * E_ * T_];                    // (b,e,t)
__device__ int    g_topidx[B_ * E_ * CAP];
__device__ float  g_topp[B_ * E_ * CAP];
__device__ float  g_h[(size_t)B_ * E_ * CAP * H_];          // 512 MB intermediate

// ---------------- gate + softmax: probs_et[b][e][t] ----------------
__global__ void gate_kernel(const float* __restrict__ x,
                            const float* __restrict__ gw) {
    int warp_global = blockIdx.x * (blockDim.x >> 5) + (threadIdx.x >> 5);
    if (warp_global >= B_ * T_) return;
    int lane = threadIdx.x & 31;
    int b = warp_global / T_;
    int t = warp_global % T_;

    const float* xr = x + (size_t)warp_global * C_;
    float acc[E_];
#pragma unroll
    for (int e = 0; e < E_; e++) acc[e] = 0.f;

    for (int c = lane; c < C_; c += 32) {
        float xv = xr[c];
        const float* g = gw + c * E_;
#pragma unroll
        for (int e = 0; e < E_; e++) acc[e] += xv * g[e];
    }
#pragma unroll
    for (int off = 16; off > 0; off >>= 1) {
#pragma unroll
        for (int e = 0; e < E_; e++)
            acc[e] += __shfl_xor_sync(0xFFFFFFFFu, acc[e], off);
    }
    // softmax over E (all lanes have full sums; lane 0 writes)
    if (lane == 0) {
        float mx = acc[0];
#pragma unroll
        for (int e = 1; e < E_; e++) mx = fmaxf(mx, acc[e]);
        float s = 0.f;
        float p[E_];
#pragma unroll
        for (int e = 0; e < E_; e++) { p[e] = expf(acc[e] - mx); s += p[e]; }
        float inv = 1.f / s;
#pragma unroll
        for (int e = 0; e < E_; e++)
            g_probs[((size_t)b * E_ + e) * T_ + t] = p[e] * inv;
    }
}

// ---------------- exact top-cap per (b,e): bitonic sort of 4096 keys ----------------
__global__ void topk_kernel() {
    __shared__ unsigned long long keys[T_];
    int be = blockIdx.x;
    const float* p = g_probs + (size_t)be * T_;

    for (int i = threadIdx.x; i < T_; i += blockDim.x) {
        unsigned fb = __float_as_uint(p[i]);   // probs > 0 -> monotonic as uint
        // tie-break: lower token index wins (matches jax top_k first-occurrence)
        keys[i] = ((unsigned long long)fb << 32) | (unsigned)(T_ - 1 - i);
    }
    __syncthreads();

    for (int k = 2; k <= T_; k <<= 1) {
        for (int j = k >> 1; j > 0; j >>= 1) {
            for (int i = threadIdx.x; i < T_; i += blockDim.x) {
                int l = i ^ j;
                if (l > i) {
                    bool up = ((i & k) == 0);   // ascending block
                    unsigned long long a = keys[i], c = keys[l];
                    if ((a > c) == up) { keys[i] = c; keys[l] = a; }
                }
            }
            __syncthreads();
        }
    }
    // ascending sorted: top CAP at the end
    for (int i = threadIdx.x; i < CAP; i += blockDim.x) {
        unsigned long long kk = keys[T_ - 1 - i];
        int idx = T_ - 1 - (int)(kk & 0xFFFFFFFFull);
        g_topidx[be * CAP + i] = idx;
        g_topp[be * CAP + i]   = __uint_as_float((unsigned)(kk >> 32));
    }
}

// ---------------- GEMM1: h = gelu(xin @ w1[e]), TF32 wmma ----------------
// Per (b,e): M=CAP=1024, K=C=1024, N=H=4096. Block 128x128, BK=32, 8 warps.
__global__ void __launch_bounds__(256) gemm1_kernel(const float* __restrict__ x,
                                                    const float* __restrict__ w1) {
    const int be = blockIdx.z;
    const int b  = be >> 3;
    const int e  = be & 7;
    const int m0 = blockIdx.y * 128;
    const int n0 = blockIdx.x * 128;

    __shared__ float As[128][36];   // ld 36 floats (144B, 16B-multiple)
    __shared__ float Bs[32][132];

    const int tid = threadIdx.x;

    // A load assignment: 2 threads/row, 16 floats each
    const int arow_i = tid >> 1;
    const int acol0  = (tid & 1) * 16;
    const int tok    = g_topidx[be * CAP + m0 + arow_i];
    const float* arow = x + ((size_t)b * T_ + tok) * C_;

    // B load assignment: 8 threads/row, 16 floats each (row = k, 32 rows)
    const int brow  = tid >> 3;
    const int bcol0 = (tid & 7) * 16;
    const float* wptr = w1 + (size_t)e * C_ * H_;

    wmma::fragment<wmma::accumulator, 16, 16, 8, float> acc[2][4];
#pragma unroll
    for (int i = 0; i < 2; i++)
#pragma unroll
        for (int j = 0; j < 4; j++) wmma::fill_fragment(acc[i][j], 0.f);

    const int w  = tid >> 5;
    const int wm = (w >> 1) * 32;   // 4 warps along M
    const int wn = (w & 1) * 64;    // 2 warps along N

    for (int k0 = 0; k0 < C_; k0 += 32) {
#pragma unroll
        for (int q = 0; q < 4; q++) {
            float4 v = *(const float4*)(arow + k0 + acol0 + q * 4);
            As[arow_i][acol0 + q * 4 + 0] = wmma::__float_to_tf32(v.x);
            As[arow_i][acol0 + q * 4 + 1] = wmma::__float_to_tf32(v.y);
            As[arow_i][acol0 + q * 4 + 2] = wmma::__float_to_tf32(v.z);
            As[arow_i][acol0 + q * 4 + 3] = wmma::__float_to_tf32(v.w);
        }
#pragma unroll
        for (int q = 0; q < 4; q++) {
            float4 v = *(const float4*)(wptr + (size_t)(k0 + brow) * H_ + n0 + bcol0 + q * 4);
            Bs[brow][bcol0 + q * 4 + 0] = wmma::__float_to_tf32(v.x);
            Bs[brow][bcol0 + q * 4 + 1] = wmma::__float_to_tf32(v.y);
            Bs[brow][bcol0 + q * 4 + 2] = wmma::__float_to_tf32(v.z);
            Bs[brow][bcol0 + q * 4 + 3] = wmma::__float_to_tf32(v.w);
        }
        __syncthreads();

#pragma unroll
        for (int kk = 0; kk < 4; kk++) {
            wmma::fragment<wmma::matrix_a, 16, 16, 8, wmma::precision::tf32, wmma::row_major> af[2];
            wmma::fragment<wmma::matrix_b, 16, 16, 8, wmma::precision::tf32, wmma::row_major> bf[4];
            wmma::load_matrix_sync(af[0], &As[wm][kk * 8], 36);
            wmma::load_matrix_sync(af[1], &As[wm + 16][kk * 8], 36);
#pragma unroll
            for (int j = 0; j < 4; j++)
                wmma::load_matrix_sync(bf[j], &Bs[kk * 8][wn + j * 16], 132);
#pragma unroll
            for (int i = 0; i < 2; i++)
#pragma unroll
                for (int j = 0; j < 4; j++)
                    wmma::mma_sync(acc[i][j], af[i], bf[j], acc[i][j]);
        }
        __syncthreads();
    }

    // epilogue: exact GELU (elementwise -> fragment-layout independent), store to g_h
    float* hout = g_h + ((size_t)be * CAP + m0) * H_ + n0;
#pragma unroll
    for (int i = 0; i < 2; i++)
#pragma unroll
        for (int j = 0; j < 4; j++) {
#pragma unroll
            for (int q = 0; q < acc[i][j].num_elements; q++) {
                float v = acc[i][j].x[q];
                acc[i][j].x[q] = 0.5f * v * (1.f + erff(v * 0.70710678118654752f));
            }
            wmma::store_matrix_sync(hout + (size_t)(wm + i * 16) * H_ + wn + j * 16,
                                    acc[i][j], H_, wmma::mem_row_major);
        }
}

// ---------------- GEMM2: y = (h @ w2[e]) * p, scatter-add into out ----------------
// Per (b,e): M=1024, K=H=4096, N=C=1024. Block 128x64, BK=32, 8 warps.
__global__ void __launch_bounds__(256) gemm2_kernel(const float* __restrict__ w2,
                                                    float* __restrict__ out) {
    const int be = blockIdx.z;
    const int b  = be >> 3;
    const int e  = be & 7;
    const int m0 = blockIdx.y * 128;
    const int n0 = blockIdx.x * 64;

    __shared__ float smem[8192];                         // 32 KB (max of tiles, epilogue)
    float (*As)[36] = (float(*)[36])smem;                // 128*36 = 4608 floats
    float (*Bs)[68] = (float(*)[68])(smem + 4608);       // 32*68  = 2176 floats

    const int tid = threadIdx.x;

    const int arow_i = tid >> 1;
    const int acol0  = (tid & 1) * 16;
    const float* arow = g_h + ((size_t)be * CAP + m0 + arow_i) * H_;

    const int brow  = tid >> 3;          // 0..31 (k)
    const int bcol0 = (tid & 7) * 8;     // 8 floats/thread
    const float* wptr = w2 + (size_t)e * H_ * C_;

    wmma::fragment<wmma::accumulator, 16, 16, 8, float> acc[2][2];
#pragma unroll
    for (int i = 0; i < 2; i++)
#pragma unroll
        for (int j = 0; j < 2; j++) wmma::fill_fragment(acc[i][j], 0.f);

    const int w  = tid >> 5;
    const int wm = (w >> 1) * 32;
    const int wn = (w & 1) * 32;

    for (int k0 = 0; k0 < H_; k0 += 32) {
#pragma unroll
        for (int q = 0; q < 4; q++) {
            float4 v = *(const float4*)(arow + k0 + acol0 + q * 4);
            As[arow_i][acol0 + q * 4 + 0] = wmma::__float_to_tf32(v.x);
            As[arow_i][acol0 + q * 4 + 1] = wmma::__float_to_tf32(v.y);
            As[arow_i][acol0 + q * 4 + 2] = wmma::__float_to_tf32(v.z);
            As[arow_i][acol0 + q * 4 + 3] = wmma::__float_to_tf32(v.w);
        }
#pragma unroll
        for (int q = 0; q < 2; q++) {
            float4 v = *(const float4*)(wptr + (size_t)(k0 + brow) * C_ + n0 + bcol0 + q * 4);
            Bs[brow][bcol0 + q * 4 + 0] = wmma::__float_to_tf32(v.x);
            Bs[brow][bcol0 + q * 4 + 1] = wmma::__float_to_tf32(v.y);
            Bs[brow][bcol0 + q * 4 + 2] = wmma::__float_to_tf32(v.z);
            Bs[brow][bcol0 + q * 4 + 3] = wmma::__float_to_tf32(v.w);
        }
        __syncthreads();

#pragma unroll
        for (int kk = 0; kk < 4; kk++) {
            wmma::fragment<wmma::matrix_a, 16, 16, 8, wmma::precision::tf32, wmma::row_major> af[2];
            wmma::fragment<wmma::matrix_b, 16, 16, 8, wmma::precision::tf32, wmma::row_major> bf[2];
            wmma::load_matrix_sync(af[0], &As[wm][kk * 8], 36);
            wmma::load_matrix_sync(af[1], &As[wm + 16][kk * 8], 36);
            wmma::load_matrix_sync(bf[0], &Bs[kk * 8][wn], 68);
            wmma::load_matrix_sync(bf[1], &Bs[kk * 8][wn + 16], 68);
#pragma unroll
            for (int i = 0; i < 2; i++)
#pragma unroll
                for (int j = 0; j < 2; j++)
                    wmma::mma_sync(acc[i][j], af[i], bf[j], acc[i][j]);
        }
        __syncthreads();
    }

    // epilogue: stage tile in smem (reuse), scale by p[m], scatter-add
    float* epi = smem;   // 128*64 floats = 32 KB
#pragma unroll
    for (int i = 0; i < 2; i++)
#pragma unroll
        for (int j = 0; j < 2; j++)
            wmma::store_matrix_sync(epi + (size_t)(wm + i * 16) * 64 + wn + j * 16,
                                    acc[i][j], 64, wmma::mem_row_major);
    __syncthreads();

    for (int idx = tid; idx < 128 * 64; idx += 256) {
        int m = idx >> 6;
        int n = idx & 63;
        int tok  = g_topidx[be * CAP + m0 + m];
        float pv = g_topp[be * CAP + m0 + m];
        atomicAdd(out + ((size_t)b * T_ + tok) * C_ + n0 + n, epi[idx] * pv);
    }
}

// ---------------- launch ----------------
extern "C" void kernel_launch(void* const* d_in, const int* in_sizes, int n_in,
                              void* d_out, int out_size) {
    const float* x  = (const float*)d_in[0];
    const float* gw = (const float*)d_in[1];
    const float* w1 = (const float*)d_in[2];
    const float* w2 = (const float*)d_in[3];
    float* out = (float*)d_out;

    cudaMemsetAsync(out, 0, (size_t)out_size * sizeof(float), 0);

    // gate: 16384 tokens, 8 warps/block
    gate_kernel<<<(B_ * T_) / 8, 256>>>(x, gw);

    // top-k: one block per (b,e)
    topk_kernel<<<B_ * E_, 512>>>();

    // GEMM1: h = gelu(xin @ w1)
    {
        dim3 grid(H_ / 128, CAP / 128, B_ * E_);
        gemm1_kernel<<<grid, 256>>>(x, w1);
    }
    // GEMM2: out += (h @ w2) * p (scatter)
    {
        dim3 grid(C_ / 64, CAP / 128, B_ * E_);
        gemm2_kernel<<<grid, 256>>>(w2, out);
    }
}

// round 3
// speedup vs baseline: 2.3917x; 2.3917x over previous
#include <cuda_runtime.h>
#include <cuda_fp16.h>
#include <cstdint>
#include <math.h>

// Problem constants
#define B_   4
#define T_   4096
#define C_   1024
#define H_   4096
#define E_   8
#define CAP  1024   // int(2.0 * T / E)

#include <mma.h>
using namespace nvcuda;

// ---------------- device scratch (no allocations allowed) ----------------
__device__ float  g_probs[B_ * E_ * T_];
__device__ int    g_topidx[B_ * E_ * CAP];
__device__ float  g_topp[B_ * E_ * CAP];
__device__ __half g_xh[(size_t)B_ * T_ * C_];            // 32 MB  x in half
__device__ __half g_w1h[(size_t)E_ * C_ * H_];           // 64 MB  w1 in half
__device__ __half g_w2h[(size_t)E_ * H_ * C_];           // 64 MB  w2 in half
__device__ __half g_h[(size_t)B_ * E_ * CAP * H_];       // 256 MB intermediate (half)

// ---------------- fp32 -> fp16 converter (8 elems / thread) ----------------
__global__ void f2h_kernel(const float* __restrict__ src, __half* __restrict__ dst,
                           size_t n8) {
    size_t i = (size_t)blockIdx.x * blockDim.x + threadIdx.x;
    if (i >= n8) return;
    float4 a = ((const float4*)src)[2 * i];
    float4 b = ((const float4*)src)[2 * i + 1];
    __half2 h0 = __floats2half2_rn(a.x, a.y);
    __half2 h1 = __floats2half2_rn(a.z, a.w);
    __half2 h2 = __floats2half2_rn(b.x, b.y);
    __half2 h3 = __floats2half2_rn(b.z, b.w);
    uint4 o;
    o.x = *(uint32_t*)&h0; o.y = *(uint32_t*)&h1;
    o.z = *(uint32_t*)&h2; o.w = *(uint32_t*)&h3;
    ((uint4*)dst)[i] = o;
}

// ---------------- gate + softmax ----------------
__global__ void gate_kernel(const float* __restrict__ x,
                            const float* __restrict__ gw) {
    int warp_global = blockIdx.x * (blockDim.x >> 5) + (threadIdx.x >> 5);
    if (warp_global >= B_ * T_) return;
    int lane = threadIdx.x & 31;
    int b = warp_global / T_;
    int t = warp_global % T_;

    const float* xr = x + (size_t)warp_global * C_;
    float acc[E_];
#pragma unroll
    for (int e = 0; e < E_; e++) acc[e] = 0.f;
    for (int c = lane; c < C_; c += 32) {
        float xv = xr[c];
        const float* g = gw + c * E_;
#pragma unroll
        for (int e = 0; e < E_; e++) acc[e] += xv * g[e];
    }
#pragma unroll
    for (int off = 16; off > 0; off >>= 1) {
#pragma unroll
        for (int e = 0; e < E_; e++)
            acc[e] += __shfl_xor_sync(0xFFFFFFFFu, acc[e], off);
    }
    if (lane == 0) {
        float mx = acc[0];
#pragma unroll
        for (int e = 1; e < E_; e++) mx = fmaxf(mx, acc[e]);
        float s = 0.f, p[E_];
#pragma unroll
        for (int e = 0; e < E_; e++) { p[e] = expf(acc[e] - mx); s += p[e]; }
        float inv = 1.f / s;
#pragma unroll
        for (int e = 0; e < E_; e++)
            g_probs[((size_t)b * E_ + e) * T_ + t] = p[e] * inv;
    }
}

// ---------------- exact top-cap bitonic sort (known correct) ----------------
__global__ void topk_kernel() {
    __shared__ unsigned long long keys[T_];
    int be = blockIdx.x;
    const float* p = g_probs + (size_t)be * T_;

    for (int i = threadIdx.x; i < T_; i += blockDim.x) {
        unsigned fb = __float_as_uint(p[i]);
        keys[i] = ((unsigned long long)fb << 32) | (unsigned)(T_ - 1 - i);
    }
    __syncthreads();
    for (int k = 2; k <= T_; k <<= 1) {
        for (int j = k >> 1; j > 0; j >>= 1) {
            for (int i = threadIdx.x; i < T_; i += blockDim.x) {
                int l = i ^ j;
                if (l > i) {
                    bool up = ((i & k) == 0);
                    unsigned long long a = keys[i], c = keys[l];
                    if ((a > c) == up) { keys[i] = c; keys[l] = a; }
                }
            }
            __syncthreads();
        }
    }
    for (int i = threadIdx.x; i < CAP; i += blockDim.x) {
        unsigned long long kk = keys[T_ - 1 - i];
        int idx = T_ - 1 - (int)(kk & 0xFFFFFFFFull);
        g_topidx[be * CAP + i] = idx;
        g_topp[be * CAP + i]   = __uint_as_float((unsigned)(kk >> 32));
    }
}

// ---------------- cp.async helpers ----------------
__device__ __forceinline__ uint32_t smem_u32(const void* p) {
    uint32_t a;
    asm("{ .reg .u64 t; cvta.to.shared.u64 t, %1; cvt.u32.u64 %0, t; }" : "=r"(a) : "l"(p));
    return a;
}
__device__ __forceinline__ void cpa16(uint32_t dst, const void* src) {
    asm volatile("cp.async.cg.shared.global [%0], [%1], 16;" :: "r"(dst), "l"(src));
}
#define CP_COMMIT() asm volatile("cp.async.commit_group;" ::: "memory")
#define CP_WAIT2()  asm volatile("cp.async.wait_group 2;" ::: "memory")
#define CP_WAIT0()  asm volatile("cp.async.wait_group 0;" ::: "memory")

// ================= pipelined fp16 wmma GEMM =================
// CTA tile 128x128, BK=32, 3-stage cp.async pipeline, 8 warps (warp tile 32x64).
// All gmem operands are half. GATHER: A rows via g_topidx from g_xh.
// GELU_STORE: gelu + store half to g_h; else: scale by top_p + atomic scatter-add.
// smem layout (dynamic, 67584 B):
//   [0      .. 30720)  A stages: 3 x 128 rows x 40 halves (80 B rows)
//   [30720  .. 56832)  B stages: 3 x 32 rows x 136 halves (272 B rows)
//   epilogue reuse: fp32 tile 128 x 132
#define A_STAGE 10240
#define B_STAGE 8704
#define B_BASE  30720

template<int KTOT, int LDN, bool GATHER, bool GELU_STORE>
__global__ void __launch_bounds__(256, 2)
moe_gemm(const __half* __restrict__ Ah, const __half* __restrict__ Wh,
         float* __restrict__ Out) {
    constexpr int KI = KTOT / 32;
    extern __shared__ char sm[];

    const int tid = threadIdx.x;
    const int ei = blockIdx.z >> 2;
    const int bi = blockIdx.z & 3;
    const int be = bi * E_ + ei;                 // scratch index order
    const int m0 = blockIdx.y * 128;
    const int n0 = blockIdx.x * 128;

    // ---- per-thread load assignments (fixed across k-iters) ----
    const int ar = tid >> 1;                     // A row 0..127
    const int ac = (tid & 1) * 16;               // A col half-index {0,16}
    const __half* aptr;
    if (GATHER) {
        int tok = g_topidx[be * CAP + m0 + ar];
        aptr = Ah + ((size_t)bi * T_ + tok) * C_ + ac;
    } else {
        aptr = g_h + ((size_t)be * CAP + m0 + ar) * (size_t)H_ + ac;
    }
    const uint32_t a_sm = smem_u32(sm) + (uint32_t)(ar * 80 + ac * 2);

    const int br = tid >> 3;                     // B k-row 0..31
    const int bc = (tid & 7) * 16;               // B col half-index
    const __half* bptr = Wh + (size_t)ei * KTOT * LDN + (size_t)br * LDN + n0 + bc;
    const uint32_t b_sm = smem_u32(sm) + B_BASE + (uint32_t)(br * 272 + bc * 2);

    wmma::fragment<wmma::accumulator, 16, 16, 16, float> acc[2][4];
#pragma unroll
    for (int i = 0; i < 2; i++)
#pragma unroll
        for (int j = 0; j < 4; j++) wmma::fill_fragment(acc[i][j], 0.f);

    const int w  = tid >> 5;
    const int wm = (w >> 1) * 32;                // 4 warps along M
    const int wn = (w & 1) * 64;                 // 2 warps along N

    auto issue = [&](int i) {
        const int s = i % 3;
        const int k0 = i * 32;
        cpa16(a_sm + s * A_STAGE,      aptr + k0);
        cpa16(a_sm + s * A_STAGE + 16, aptr + k0 + 8);
        const __half* bsrc = bptr + (size_t)k0 * LDN;
        cpa16(b_sm + s * B_STAGE,      bsrc);
        cpa16(b_sm + s * B_STAGE + 16, bsrc + 8);
        CP_COMMIT();
    };

    issue(0); issue(1); issue(2);

    for (int i = 0; i < KI; ++i) {
        CP_WAIT2();
        __syncthreads();
        const __half* As = (const __half*)(sm + (i % 3) * A_STAGE);
        const __half* Bs = (const __half*)(sm + B_BASE + (i % 3) * B_STAGE);
#pragma unroll
        for (int kk = 0; kk < 2; ++kk) {
            wmma::fragment<wmma::matrix_a, 16, 16, 16, __half, wmma::row_major> af[2];
            wmma::fragment<wmma::matrix_b, 16, 16, 16, __half, wmma::row_major> bf[4];
            wmma::load_matrix_sync(af[0], As + (size_t)wm * 40 + kk * 16, 40);
            wmma::load_matrix_sync(af[1], As + (size_t)(wm + 16) * 40 + kk * 16, 40);
#pragma unroll
            for (int j = 0; j < 4; ++j)
                wmma::load_matrix_sync(bf[j], Bs + (size_t)kk * 16 * 136 + wn + j * 16, 136);
#pragma unroll
            for (int ii = 0; ii < 2; ++ii)
#pragma unroll
                for (int j = 0; j < 4; ++j)
                    wmma::mma_sync(acc[ii][j], af[ii], bf[j], acc[ii][j]);
        }
        __syncthreads();
        if (i + 3 < KI) issue(i + 3);
    }
    CP_WAIT0();
    __syncthreads();

    // ---- epilogue: stage fp32 tile 128x132 in smem ----
    float* Eb = (float*)sm;
#pragma unroll
    for (int ii = 0; ii < 2; ++ii)
#pragma unroll
        for (int j = 0; j < 4; ++j)
            wmma::store_matrix_sync(&Eb[(size_t)(wm + ii * 16) * 132 + wn + j * 16],
                                    acc[ii][j], 132, wmma::mem_row_major);
    __syncthreads();

    if (GELU_STORE) {
        const size_t rowbase = (size_t)be * CAP + m0;
        for (int idx = tid; idx < 128 * 16; idx += 256) {
            const int r  = idx >> 4;
            const int c0 = (idx & 15) * 8;
            __half hv[8];
#pragma unroll
            for (int c = 0; c < 8; ++c) {
                float v = Eb[(size_t)r * 132 + c0 + c];
                v = 0.5f * v * (1.f + erff(v * 0.70710678118654752f));
                hv[c] = __float2half(v);
            }
            *(uint4*)&g_h[(rowbase + r) * (size_t)H_ + n0 + c0] = *(uint4*)hv;
        }
    } else {
        for (int idx = tid; idx < 128 * 128; idx += 256) {
            const int m = idx >> 7;
            const int n = idx & 127;
            const int tok  = g_topidx[be * CAP + m0 + m];
            const float pv = g_topp[be * CAP + m0 + m];
            atomicAdd(Out + ((size_t)bi * T_ + tok) * C_ + n0 + n,
                      Eb[(size_t)m * 132 + n] * pv);
        }
    }
}

// ---------------- launch ----------------
extern "C" void kernel_launch(void* const* d_in, const int* in_sizes, int n_in,
                              void* d_out, int out_size) {
    const float* x  = (const float*)d_in[0];
    const float* gw = (const float*)d_in[1];
    const float* w1 = (const float*)d_in[2];
    const float* w2 = (const float*)d_in[3];
    float* out = (float*)d_out;

    const int SMEM = 128 * 132 * 4;   // 67584 B (covers pipeline 56832 B too)
    cudaFuncSetAttribute(moe_gemm<C_, H_, true,  true >,
                         cudaFuncAttributeMaxDynamicSharedMemorySize, SMEM);
    cudaFuncSetAttribute(moe_gemm<H_, C_, false, false>,
                         cudaFuncAttributeMaxDynamicSharedMemorySize, SMEM);

    cudaMemsetAsync(out, 0, (size_t)out_size * sizeof(float), 0);

    // fp32 -> fp16 conversions (x, w1, w2)
    {
        __half* xh;  cudaGetSymbolAddress((void**)&xh,  g_xh);
        __half* w1h; cudaGetSymbolAddress((void**)&w1h, g_w1h);
        __half* w2h; cudaGetSymbolAddress((void**)&w2h, g_w2h);
        size_t nx = (size_t)B_ * T_ * C_ / 8;
        size_t nw = (size_t)E_ * C_ * H_ / 8;
        f2h_kernel<<<(unsigned)((nx + 255) / 256), 256>>>(x,  xh,  nx);
        f2h_kernel<<<(unsigned)((nw + 255) / 256), 256>>>(w1, w1h, nw);
        f2h_kernel<<<(unsigned)((nw + 255) / 256), 256>>>(w2, w2h, nw);
    }

    gate_kernel<<<(B_ * T_) / 8, 256>>>(x, gw);
    topk_kernel<<<B_ * E_, 512>>>();

    __half* xh;  cudaGetSymbolAddress((void**)&xh,  g_xh);
    __half* w1h; cudaGetSymbolAddress((void**)&w1h, g_w1h);
    __half* w2h; cudaGetSymbolAddress((void**)&w2h, g_w2h);

    // GEMM1: h = gelu(xin @ w1)   [M=1024, N=4096, K=1024] per (b,e)
    {
        dim3 grid(H_ / 128, CAP / 128, B_ * E_);
        moe_gemm<C_, H_, true, true><<<grid, 256, SMEM>>>(xh, w1h, nullptr);
    }
    // GEMM2: out += (h @ w2) * p  [M=1024, N=1024, K=4096] per (b,e)
    {
        dim3 grid(C_ / 128, CAP / 128, B_ * E_);
        moe_gemm<H_, C_, false, false><<<grid, 256, SMEM>>>(nullptr, w2h, out);
    }
}

// round 13
// speedup vs baseline: 3.7781x; 1.5797x over previous
#include <cuda_runtime.h>
#include <cuda_fp16.h>
#include <cstdint>
#include <math.h>

// Problem constants
#define B_   4
#define T_   4096
#define C_   1024
#define H_   4096
#define E_   8
#define CAP  1024   // int(2.0 * T / E)

// ---------------- device scratch (no allocations allowed) ----------------
__device__ float  g_probs[B_ * E_ * T_];
__device__ int    g_topidx[B_ * E_ * CAP];
__device__ float  g_topp[B_ * E_ * CAP];
__device__ __half g_xh[(size_t)B_ * T_ * C_];            // 32 MB
__device__ __half g_w1h[(size_t)E_ * C_ * H_];           // 64 MB
__device__ __half g_w2h[(size_t)E_ * H_ * C_];           // 64 MB
__device__ __half g_h[(size_t)B_ * E_ * CAP * H_];       // 256 MB intermediate

// ---------------- fp32 -> fp16 converter ----------------
__global__ void f2h_kernel(const float* __restrict__ src, __half* __restrict__ dst,
                           size_t n8) {
    size_t i = (size_t)blockIdx.x * blockDim.x + threadIdx.x;
    if (i >= n8) return;
    float4 a = ((const float4*)src)[2 * i];
    float4 b = ((const float4*)src)[2 * i + 1];
    __half2 h0 = __floats2half2_rn(a.x, a.y);
    __half2 h1 = __floats2half2_rn(a.z, a.w);
    __half2 h2 = __floats2half2_rn(b.x, b.y);
    __half2 h3 = __floats2half2_rn(b.z, b.w);
    uint4 o;
    o.x = *(uint32_t*)&h0; o.y = *(uint32_t*)&h1;
    o.z = *(uint32_t*)&h2; o.w = *(uint32_t*)&h3;
    ((uint4*)dst)[i] = o;
}

// ---------------- gate + softmax (vectorized, gw in smem) ----------------
__global__ void __launch_bounds__(256) gate_kernel(const float* __restrict__ x,
                                                   const float* __restrict__ gw) {
    __shared__ float4 sgw[C_ * 2];          // gw row c -> 2 float4 (8 experts)
    const int tid = threadIdx.x;
    for (int i = tid; i < C_ * 2; i += 256) sgw[i] = ((const float4*)gw)[i];
    __syncthreads();

    const int warp = tid >> 5, lane = tid & 31;
    const int token = blockIdx.x * 8 + warp;          // 8 tokens / block
    const int b = token / T_, t = token % T_;
    const float4* xr = (const float4*)(x + (size_t)token * C_);

    float acc[E_];
#pragma unroll
    for (int e = 0; e < E_; e++) acc[e] = 0.f;

#pragma unroll
    for (int it = 0; it < 8; ++it) {
        float4 xv = xr[lane + 32 * it];
        int c0 = (lane + 32 * it) * 4;
#pragma unroll
        for (int r = 0; r < 4; ++r) {
            float xs = (&xv.x)[r];
            float4 g0 = sgw[(c0 + r) * 2];
            float4 g1 = sgw[(c0 + r) * 2 + 1];
            acc[0] += xs * g0.x; acc[1] += xs * g0.y;
            acc[2] += xs * g0.z; acc[3] += xs * g0.w;
            acc[4] += xs * g1.x; acc[5] += xs * g1.y;
            acc[6] += xs * g1.z; acc[7] += xs * g1.w;
        }
    }
#pragma unroll
    for (int off = 16; off > 0; off >>= 1) {
#pragma unroll
        for (int e = 0; e < E_; e++)
            acc[e] += __shfl_xor_sync(0xFFFFFFFFu, acc[e], off);
    }
    if (lane == 0) {
        float mx = acc[0];
#pragma unroll
        for (int e = 1; e < E_; e++) mx = fmaxf(mx, acc[e]);
        float s = 0.f, p[E_];
#pragma unroll
        for (int e = 0; e < E_; e++) { p[e] = expf(acc[e] - mx); s += p[e]; }
        float inv = 1.f / s;
#pragma unroll
        for (int e = 0; e < E_; e++)
            g_probs[((size_t)b * E_ + e) * T_ + t] = p[e] * inv;
    }
}

// ---------------- exact top-cap bitonic sort (known correct) ----------------
__global__ void topk_kernel() {
    __shared__ unsigned long long keys[T_];
    int be = blockIdx.x;
    const float* p = g_probs + (size_t)be * T_;

    for (int i = threadIdx.x; i < T_; i += blockDim.x) {
        unsigned fb = __float_as_uint(p[i]);
        keys[i] = ((unsigned long long)fb << 32) | (unsigned)(T_ - 1 - i);
    }
    __syncthreads();
    for (int k = 2; k <= T_; k <<= 1) {
        for (int j = k >> 1; j > 0; j >>= 1) {
            for (int i = threadIdx.x; i < T_; i += blockDim.x) {
                int l = i ^ j;
                if (l > i) {
                    bool up = ((i & k) == 0);
                    unsigned long long a = keys[i], c = keys[l];
                    if ((a > c) == up) { keys[i] = c; keys[l] = a; }
                }
            }
            __syncthreads();
        }
    }
    for (int i = threadIdx.x; i < CAP; i += blockDim.x) {
        unsigned long long kk = keys[T_ - 1 - i];
        int idx = T_ - 1 - (int)(kk & 0xFFFFFFFFull);
        g_topidx[be * CAP + i] = idx;
        g_topp[be * CAP + i]   = __uint_as_float((unsigned)(kk >> 32));
    }
}

// ---------------- PTX helpers ----------------
__device__ __forceinline__ uint32_t smem_u32(const void* p) {
    uint32_t a;
    asm("{ .reg .u64 t; cvta.to.shared.u64 t, %1; cvt.u32.u64 %0, t; }" : "=r"(a) : "l"(p));
    return a;
}
__device__ __forceinline__ void cpa16(uint32_t dst, const void* src) {
    asm volatile("cp.async.cg.shared.global [%0], [%1], 16;" :: "r"(dst), "l"(src));
}
#define CP_COMMIT() asm volatile("cp.async.commit_group;" ::: "memory")
#define CP_WAIT2()  asm volatile("cp.async.wait_group 2;" ::: "memory")
#define CP_WAIT0()  asm volatile("cp.async.wait_group 0;" ::: "memory")

__device__ __forceinline__ void ldsm4(uint32_t* r, uint32_t addr) {
    asm volatile("ldmatrix.sync.aligned.m8n8.x4.shared.b16 {%0,%1,%2,%3}, [%4];"
                 : "=r"(r[0]), "=r"(r[1]), "=r"(r[2]), "=r"(r[3]) : "r"(addr));
}
__device__ __forceinline__ void ldsm4t(uint32_t* r, uint32_t addr) {
    asm volatile("ldmatrix.sync.aligned.m8n8.x4.trans.shared.b16 {%0,%1,%2,%3}, [%4];"
                 : "=r"(r[0]), "=r"(r[1]), "=r"(r[2]), "=r"(r[3]) : "r"(addr));
}
__device__ __forceinline__ void mma16816(float* c, const uint32_t* a,
                                         uint32_t b0, uint32_t b1) {
    asm volatile("mma.sync.aligned.m16n8k16.row.col.f32.f16.f16.f32 "
                 "{%0,%1,%2,%3}, {%4,%5,%6,%7}, {%8,%9}, {%0,%1,%2,%3};"
                 : "+f"(c[0]), "+f"(c[1]), "+f"(c[2]), "+f"(c[3])
                 : "r"(a[0]), "r"(a[1]), "r"(a[2]), "r"(a[3]), "r"(b0), "r"(b1));
}

// ================= pipelined fp16 mma.sync GEMM =================
// CTA tile 128x128, BK=32, 3-stage cp.async. 8 warps = 2(M) x 4(N),
// warp tile 64x32 via ldmatrix.x4 + mma.m16n8k16.
// smem: A stages 3 x 128rows x 80B = 30720; B stages 3 x 32rows x 272B = 26112.
#define A_STAGE 10240
#define B_STAGE 8704
#define B_BASE  30720

template<int KTOT, int LDN, bool GATHER, bool GELU_STORE>
__global__ void __launch_bounds__(256, 2)
moe_gemm(const __half* __restrict__ Ah, const __half* __restrict__ Wh,
         float* __restrict__ Out) {
    constexpr int KI = KTOT / 32;
    extern __shared__ char sm[];

    const int tid = threadIdx.x;
    const int ei = blockIdx.z >> 2;
    const int bi = blockIdx.z & 3;
    const int be = bi * E_ + ei;
    const int m0 = blockIdx.y * 128;
    const int n0 = blockIdx.x * 128;

    // ---- cp.async load assignments ----
    const int ar = tid >> 1;
    const int ac = (tid & 1) * 16;
    const __half* aptr;
    if (GATHER) {
        int tok = g_topidx[be * CAP + m0 + ar];
        aptr = Ah + ((size_t)bi * T_ + tok) * C_ + ac;
    } else {
        aptr = g_h + ((size_t)be * CAP + m0 + ar) * (size_t)H_ + ac;
    }
    const uint32_t smb = smem_u32(sm);
    const uint32_t a_sm = smb + (uint32_t)(ar * 80 + ac * 2);

    const int br = tid >> 3;
    const int bc = (tid & 7) * 16;
    const __half* bptr = Wh + (size_t)ei * KTOT * LDN + (size_t)br * LDN + n0 + bc;
    const uint32_t b_sm = smb + B_BASE + (uint32_t)(br * 272 + bc * 2);

    // ---- mma thread mapping ----
    const int w  = tid >> 5;
    const int l  = tid & 31;
    const int wm = (w >> 2) * 64;               // 2 warps along M
    const int wn = (w & 3) * 32;                // 4 warps along N

    // ldmatrix lane offsets (bytes)
    const uint32_t a_lane = (uint32_t)((l & 15) * 80 + (l >> 4) * 16);
    const uint32_t b_lane = (uint32_t)((l & 7) * 272 + ((l >> 3) & 1) * (8 * 272) + (l >> 4) * 16);

    float acc[4][4][4];
#pragma unroll
    for (int i = 0; i < 4; i++)
#pragma unroll
        for (int j = 0; j < 4; j++)
#pragma unroll
            for (int r = 0; r < 4; r++) acc[i][j][r] = 0.f;

    auto issue = [&](int i) {
        const int s = i % 3;
        const int k0 = i * 32;
        cpa16(a_sm + s * A_STAGE,      aptr + k0);
        cpa16(a_sm + s * A_STAGE + 16, aptr + k0 + 8);
        const __half* bsrc = bptr + (size_t)k0 * LDN;
        cpa16(b_sm + s * B_STAGE,      bsrc);
        cpa16(b_sm + s * B_STAGE + 16, bsrc + 8);
        CP_COMMIT();
    };

    issue(0); issue(1); issue(2);

    for (int i = 0; i < KI; ++i) {
        CP_WAIT2();
        __syncthreads();
        const uint32_t As = smb + (i % 3) * A_STAGE;
        const uint32_t Bs = smb + B_BASE + (i % 3) * B_STAGE;
#pragma unroll
        for (int kk = 0; kk < 2; ++kk) {
            uint32_t a[4][4];
#pragma unroll
            for (int i4 = 0; i4 < 4; ++i4)
                ldsm4(a[i4], As + (uint32_t)((wm + i4 * 16) * 80 + kk * 32) + a_lane);
            uint32_t bfr[2][4];
#pragma unroll
            for (int j16 = 0; j16 < 2; ++j16)
                ldsm4t(bfr[j16], Bs + (uint32_t)(kk * 16 * 272 + (wn + j16 * 16) * 2) + b_lane);
#pragma unroll
            for (int i4 = 0; i4 < 4; ++i4)
#pragma unroll
                for (int j = 0; j < 4; ++j)
                    mma16816(acc[i4][j], a[i4],
                             bfr[j >> 1][(j & 1) * 2], bfr[j >> 1][(j & 1) * 2 + 1]);
        }
        __syncthreads();
        if (i + 3 < KI) issue(i + 3);
    }
    CP_WAIT0();
    __syncthreads();

    // ---- epilogue: stage fp32 tile 128x132 in smem ----
    float* Eb = (float*)sm;
    {
        const int r0 = l >> 2;
        const int c0 = (l & 3) * 2;
#pragma unroll
        for (int i4 = 0; i4 < 4; ++i4)
#pragma unroll
            for (int j = 0; j < 4; ++j) {
                float* p0 = &Eb[(size_t)(wm + i4 * 16 + r0) * 132 + wn + j * 8 + c0];
                p0[0]   = acc[i4][j][0];
                p0[1]   = acc[i4][j][1];
                p0[8 * 132]     = acc[i4][j][2];
                p0[8 * 132 + 1] = acc[i4][j][3];
            }
    }
    __syncthreads();

    if (GELU_STORE) {
        const size_t rowbase = (size_t)be * CAP + m0;
        for (int idx = tid; idx < 128 * 16; idx += 256) {
            const int r  = idx >> 4;
            const int c0 = (idx & 15) * 8;
            __half hv[8];
#pragma unroll
            for (int c = 0; c < 8; ++c) {
                float v = Eb[(size_t)r * 132 + c0 + c];
                v = 0.5f * v * (1.f + erff(v * 0.70710678118654752f));
                hv[c] = __float2half(v);
            }
            *(uint4*)&g_h[(rowbase + r) * (size_t)H_ + n0 + c0] = *(uint4*)hv;
        }
    } else {
        for (int idx = tid; idx < 128 * 128; idx += 256) {
            const int m = idx >> 7;
            const int n = idx & 127;
            const int tok  = g_topidx[be * CAP + m0 + m];
            const float pv = g_topp[be * CAP + m0 + m];
            atomicAdd(Out + ((size_t)bi * T_ + tok) * C_ + n0 + n,
                      Eb[(size_t)m * 132 + n] * pv);
        }
    }
}

// ---------------- launch ----------------
extern "C" void kernel_launch(void* const* d_in, const int* in_sizes, int n_in,
                              void* d_out, int out_size) {
    const float* x  = (const float*)d_in[0];
    const float* gw = (const float*)d_in[1];
    const float* w1 = (const float*)d_in[2];
    const float* w2 = (const float*)d_in[3];
    float* out = (float*)d_out;

    const int SMEM = 128 * 132 * 4;   // 67584 B (covers pipeline 56832 B)
    cudaFuncSetAttribute(moe_gemm<C_, H_, true,  true >,
                         cudaFuncAttributeMaxDynamicSharedMemorySize, SMEM);
    cudaFuncSetAttribute(moe_gemm<H_, C_, false, false>,
                         cudaFuncAttributeMaxDynamicSharedMemorySize, SMEM);

    cudaMemsetAsync(out, 0, (size_t)out_size * sizeof(float), 0);

    __half* xh;  cudaGetSymbolAddress((void**)&xh,  g_xh);
    __half* w1h; cudaGetSymbolAddress((void**)&w1h, g_w1h);
    __half* w2h; cudaGetSymbolAddress((void**)&w2h, g_w2h);
    {
        size_t nx = (size_t)B_ * T_ * C_ / 8;
        size_t nw = (size_t)E_ * C_ * H_ / 8;
        f2h_kernel<<<(unsigned)((nx + 255) / 256), 256>>>(x,  xh,  nx);
        f2h_kernel<<<(unsigned)((nw + 255) / 256), 256>>>(w1, w1h, nw);
        f2h_kernel<<<(unsigned)((nw + 255) / 256), 256>>>(w2, w2h, nw);
    }

    gate_kernel<<<(B_ * T_) / 8, 256>>>(x, gw);
    topk_kernel<<<B_ * E_, 512>>>();

    // GEMM1: h = gelu(xin @ w1)   [M=1024, N=4096, K=1024] per (b,e)
    {
        dim3 grid(H_ / 128, CAP / 128, B_ * E_);
        moe_gemm<C_, H_, true, true><<<grid, 256, SMEM>>>(xh, w1h, nullptr);
    }
    // GEMM2: out += (h @ w2) * p  [M=1024, N=1024, K=4096] per (b,e)
    {
        dim3 grid(C_ / 128, CAP / 128, B_ * E_);
        moe_gemm<H_, C_, false, false><<<grid, 256, SMEM>>>(nullptr, w2h, out);
    }
}

// round 14
// speedup vs baseline: 3.9238x; 1.0386x over previous
#include <cuda_runtime.h>
#include <cuda_fp16.h>
#include <cstdint>
#include <math.h>

// Problem constants
#define B_   4
#define T_   4096
#define C_   1024
#define H_   4096
#define E_   8
#define CAP  1024   // int(2.0 * T / E)

// ---------------- device scratch (no allocations allowed) ----------------
__device__ float  g_probs[B_ * E_ * T_];
__device__ int    g_topidx[B_ * E_ * CAP];
__device__ float  g_topp[B_ * E_ * CAP];
__device__ __half g_xh[(size_t)B_ * T_ * C_];            // 32 MB
__device__ __half g_w1h[(size_t)E_ * C_ * H_];           // 64 MB
__device__ __half g_w2h[(size_t)E_ * H_ * C_];           // 64 MB
__device__ __half g_h[(size_t)B_ * E_ * CAP * H_];       // 256 MB intermediate

// ---------------- fp32 -> fp16 converter ----------------
__global__ void f2h_kernel(const float* __restrict__ src, __half* __restrict__ dst,
                           size_t n8) {
    size_t i = (size_t)blockIdx.x * blockDim.x + threadIdx.x;
    if (i >= n8) return;
    float4 a = ((const float4*)src)[2 * i];
    float4 b = ((const float4*)src)[2 * i + 1];
    __half2 h0 = __floats2half2_rn(a.x, a.y);
    __half2 h1 = __floats2half2_rn(a.z, a.w);
    __half2 h2 = __floats2half2_rn(b.x, b.y);
    __half2 h3 = __floats2half2_rn(b.z, b.w);
    uint4 o;
    o.x = *(uint32_t*)&h0; o.y = *(uint32_t*)&h1;
    o.z = *(uint32_t*)&h2; o.w = *(uint32_t*)&h3;
    ((uint4*)dst)[i] = o;
}

// ---------------- gate + softmax (transposed gw in smem, conflict-free) ----------------
__global__ void __launch_bounds__(256) gate_kernel(const float* __restrict__ x,
                                                   const float* __restrict__ gw) {
    __shared__ float sgwt[E_][C_];          // gw transposed: row e, col c
    const int tid = threadIdx.x;
    // transpose load: gw[c][e] -> sgwt[e][c]
    for (int i = tid; i < C_ * E_; i += 256) {
        int c = i >> 3, e = i & 7;
        sgwt[e][c] = gw[i];
    }
    __syncthreads();

    const int warp = tid >> 5, lane = tid & 31;
    const int token = blockIdx.x * 8 + warp;          // 8 tokens / block
    const int b = token / T_, t = token % T_;
    const float4* xr = (const float4*)(x + (size_t)token * C_);

    float acc[E_];
#pragma unroll
    for (int e = 0; e < E_; e++) acc[e] = 0.f;

#pragma unroll
    for (int it = 0; it < 8; ++it) {
        const int c4 = lane + 32 * it;                // float4 index, lane-consecutive
        float4 xv = xr[c4];
#pragma unroll
        for (int e = 0; e < E_; e++) {
            float4 g = *(const float4*)&sgwt[e][c4 * 4];   // conflict-free LDS.128
            acc[e] += xv.x * g.x + xv.y * g.y + xv.z * g.z + xv.w * g.w;
        }
    }
#pragma unroll
    for (int off = 16; off > 0; off >>= 1) {
#pragma unroll
        for (int e = 0; e < E_; e++)
            acc[e] += __shfl_xor_sync(0xFFFFFFFFu, acc[e], off);
    }
    if (lane == 0) {
        float mx = acc[0];
#pragma unroll
        for (int e = 1; e < E_; e++) mx = fmaxf(mx, acc[e]);
        float s = 0.f, p[E_];
#pragma unroll
        for (int e = 0; e < E_; e++) { p[e] = expf(acc[e] - mx); s += p[e]; }
        float inv = 1.f / s;
#pragma unroll
        for (int e = 0; e < E_; e++)
            g_probs[((size_t)b * E_ + e) * T_ + t] = p[e] * inv;
    }
}

// ---------------- exact top-cap bitonic sort (known correct) ----------------
__global__ void topk_kernel() {
    __shared__ unsigned long long keys[T_];
    int be = blockIdx.x;
    const float* p = g_probs + (size_t)be * T_;

    for (int i = threadIdx.x; i < T_; i += blockDim.x) {
        unsigned fb = __float_as_uint(p[i]);
        keys[i] = ((unsigned long long)fb << 32) | (unsigned)(T_ - 1 - i);
    }
    __syncthreads();
    for (int k = 2; k <= T_; k <<= 1) {
        for (int j = k >> 1; j > 0; j >>= 1) {
            for (int i = threadIdx.x; i < T_; i += blockDim.x) {
                int l = i ^ j;
                if (l > i) {
                    bool up = ((i & k) == 0);
                    unsigned long long a = keys[i], c = keys[l];
                    if ((a > c) == up) { keys[i] = c; keys[l] = a; }
                }
            }
            __syncthreads();
        }
    }
    for (int i = threadIdx.x; i < CAP; i += blockDim.x) {
        unsigned long long kk = keys[T_ - 1 - i];
        int idx = T_ - 1 - (int)(kk & 0xFFFFFFFFull);
        g_topidx[be * CAP + i] = idx;
        g_topp[be * CAP + i]   = __uint_as_float((unsigned)(kk >> 32));
    }
}

// ---------------- PTX helpers ----------------
__device__ __forceinline__ uint32_t smem_u32(const void* p) {
    uint32_t a;
    asm("{ .reg .u64 t; cvta.to.shared.u64 t, %1; cvt.u32.u64 %0, t; }" : "=r"(a) : "l"(p));
    return a;
}
__device__ __forceinline__ void cpa16(uint32_t dst, const void* src) {
    asm volatile("cp.async.cg.shared.global [%0], [%1], 16;" :: "r"(dst), "l"(src));
}
#define CP_COMMIT() asm volatile("cp.async.commit_group;" ::: "memory")
#define CP_WAIT2()  asm volatile("cp.async.wait_group 2;" ::: "memory")
#define CP_WAIT0()  asm volatile("cp.async.wait_group 0;" ::: "memory")

__device__ __forceinline__ void ldsm4(uint32_t* r, uint32_t addr) {
    asm volatile("ldmatrix.sync.aligned.m8n8.x4.shared.b16 {%0,%1,%2,%3}, [%4];"
                 : "=r"(r[0]), "=r"(r[1]), "=r"(r[2]), "=r"(r[3]) : "r"(addr));
}
__device__ __forceinline__ void ldsm4t(uint32_t* r, uint32_t addr) {
    asm volatile("ldmatrix.sync.aligned.m8n8.x4.trans.shared.b16 {%0,%1,%2,%3}, [%4];"
                 : "=r"(r[0]), "=r"(r[1]), "=r"(r[2]), "=r"(r[3]) : "r"(addr));
}
__device__ __forceinline__ void mma16816(float* c, const uint32_t* a,
                                         uint32_t b0, uint32_t b1) {
    asm volatile("mma.sync.aligned.m16n8k16.row.col.f32.f16.f16.f32 "
                 "{%0,%1,%2,%3}, {%4,%5,%6,%7}, {%8,%9}, {%0,%1,%2,%3};"
                 : "+f"(c[0]), "+f"(c[1]), "+f"(c[2]), "+f"(c[3])
                 : "r"(a[0]), "r"(a[1]), "r"(a[2]), "r"(a[3]), "r"(b0), "r"(b1));
}

// ================= pipelined fp16 mma.sync GEMM =================
// CTA tile 128x128, BK=32, 3-stage cp.async. 8 warps = 2(M) x 4(N),
// warp tile 64x32 via ldmatrix.x4 + mma.m16n8k16.
// smem: A stages 3 x 128rows x 80B = 30720; B stages 3 x 32rows x 272B = 26112.
#define A_STAGE 10240
#define B_STAGE 8704
#define B_BASE  30720

template<int KTOT, int LDN, bool GATHER, bool GELU_STORE>
__global__ void __launch_bounds__(256, 2)
moe_gemm(const __half* __restrict__ Ah, const __half* __restrict__ Wh,
         float* __restrict__ Out) {
    constexpr int KI = KTOT / 32;
    extern __shared__ char sm[];

    const int tid = threadIdx.x;
    const int ei = blockIdx.z >> 2;
    const int bi = blockIdx.z & 3;
    const int be = bi * E_ + ei;
    const int m0 = blockIdx.y * 128;
    const int n0 = blockIdx.x * 128;

    // ---- cp.async load assignments ----
    const int ar = tid >> 1;
    const int ac = (tid & 1) * 16;
    const __half* aptr;
    if (GATHER) {
        int tok = g_topidx[be * CAP + m0 + ar];
        aptr = Ah + ((size_t)bi * T_ + tok) * C_ + ac;
    } else {
        aptr = g_h + ((size_t)be * CAP + m0 + ar) * (size_t)H_ + ac;
    }
    const uint32_t smb = smem_u32(sm);
    const uint32_t a_sm = smb + (uint32_t)(ar * 80 + ac * 2);

    const int br = tid >> 3;
    const int bc = (tid & 7) * 16;
    const __half* bptr = Wh + (size_t)ei * KTOT * LDN + (size_t)br * LDN + n0 + bc;
    const uint32_t b_sm = smb + B_BASE + (uint32_t)(br * 272 + bc * 2);

    // ---- mma thread mapping ----
    const int w  = tid >> 5;
    const int l  = tid & 31;
    const int wm = (w >> 2) * 64;               // 2 warps along M
    const int wn = (w & 3) * 32;                // 4 warps along N

    // ldmatrix lane offsets (bytes)
    const uint32_t a_lane = (uint32_t)((l & 15) * 80 + (l >> 4) * 16);
    const uint32_t b_lane = (uint32_t)((l & 7) * 272 + ((l >> 3) & 1) * (8 * 272) + (l >> 4) * 16);

    float acc[4][4][4];
#pragma unroll
    for (int i = 0; i < 4; i++)
#pragma unroll
        for (int j = 0; j < 4; j++)
#pragma unroll
            for (int r = 0; r < 4; r++) acc[i][j][r] = 0.f;

    auto issue = [&](int i) {
        const int s = i % 3;
        const int k0 = i * 32;
        cpa16(a_sm + s * A_STAGE,      aptr + k0);
        cpa16(a_sm + s * A_STAGE + 16, aptr + k0 + 8);
        const __half* bsrc = bptr + (size_t)k0 * LDN;
        cpa16(b_sm + s * B_STAGE,      bsrc);
        cpa16(b_sm + s * B_STAGE + 16, bsrc + 8);
        CP_COMMIT();
    };

    issue(0); issue(1); issue(2);

    for (int i = 0; i < KI; ++i) {
        CP_WAIT2();
        __syncthreads();
        const uint32_t As = smb + (i % 3) * A_STAGE;
        const uint32_t Bs = smb + B_BASE + (i % 3) * B_STAGE;
#pragma unroll
        for (int kk = 0; kk < 2; ++kk) {
            uint32_t a[4][4];
#pragma unroll
            for (int i4 = 0; i4 < 4; ++i4)
                ldsm4(a[i4], As + (uint32_t)((wm + i4 * 16) * 80 + kk * 32) + a_lane);
            uint32_t bfr[2][4];
#pragma unroll
            for (int j16 = 0; j16 < 2; ++j16)
                ldsm4t(bfr[j16], Bs + (uint32_t)(kk * 16 * 272 + (wn + j16 * 16) * 2) + b_lane);
#pragma unroll
            for (int i4 = 0; i4 < 4; ++i4)
#pragma unroll
                for (int j = 0; j < 4; ++j)
                    mma16816(acc[i4][j], a[i4],
                             bfr[j >> 1][(j & 1) * 2], bfr[j >> 1][(j & 1) * 2 + 1]);
        }
        __syncthreads();
        if (i + 3 < KI) issue(i + 3);
    }
    CP_WAIT0();
    __syncthreads();

    // ---- epilogue: stage fp32 tile 128x132 in smem ----
    float* Eb = (float*)sm;
    {
        const int r0 = l >> 2;
        const int c0 = (l & 3) * 2;
#pragma unroll
        for (int i4 = 0; i4 < 4; ++i4)
#pragma unroll
            for (int j = 0; j < 4; ++j) {
                float* p0 = &Eb[(size_t)(wm + i4 * 16 + r0) * 132 + wn + j * 8 + c0];
                p0[0]   = acc[i4][j][0];
                p0[1]   = acc[i4][j][1];
                p0[8 * 132]     = acc[i4][j][2];
                p0[8 * 132 + 1] = acc[i4][j][3];
            }
    }
    __syncthreads();

    if (GELU_STORE) {
        const size_t rowbase = (size_t)be * CAP + m0;
        for (int idx = tid; idx < 128 * 16; idx += 256) {
            const int r  = idx >> 4;
            const int c0 = (idx & 15) * 8;
            __half hv[8];
#pragma unroll
            for (int c = 0; c < 8; ++c) {
                float v = Eb[(size_t)r * 132 + c0 + c];
                v = 0.5f * v * (1.f + erff(v * 0.70710678118654752f));
                hv[c] = __float2half(v);
            }
            *(uint4*)&g_h[(rowbase + r) * (size_t)H_ + n0 + c0] = *(uint4*)hv;
        }
    } else {
        for (int idx = tid; idx < 128 * 128; idx += 256) {
            const int m = idx >> 7;
            const int n = idx & 127;
            const int tok  = g_topidx[be * CAP + m0 + m];
            const float pv = g_topp[be * CAP + m0 + m];
            atomicAdd(Out + ((size_t)bi * T_ + tok) * C_ + n0 + n,
                      Eb[(size_t)m * 132 + n] * pv);
        }
    }
}

// ---------------- launch ----------------
extern "C" void kernel_launch(void* const* d_in, const int* in_sizes, int n_in,
                              void* d_out, int out_size) {
    const float* x  = (const float*)d_in[0];
    const float* gw = (const float*)d_in[1];
    const float* w1 = (const float*)d_in[2];
    const float* w2 = (const float*)d_in[3];
    float* out = (float*)d_out;

    const int SMEM = 128 * 132 * 4;   // 67584 B (covers pipeline 56832 B)
    cudaFuncSetAttribute(moe_gemm<C_, H_, true,  true >,
                         cudaFuncAttributeMaxDynamicSharedMemorySize, SMEM);
    cudaFuncSetAttribute(moe_gemm<H_, C_, false, false>,
                         cudaFuncAttributeMaxDynamicSharedMemorySize, SMEM);

    cudaMemsetAsync(out, 0, (size_t)out_size * sizeof(float), 0);

    __half* xh;  cudaGetSymbolAddress((void**)&xh,  g_xh);
    __half* w1h; cudaGetSymbolAddress((void**)&w1h, g_w1h);
    __half* w2h; cudaGetSymbolAddress((void**)&w2h, g_w2h);
    {
        size_t nx = (size_t)B_ * T_ * C_ / 8;
        size_t nw = (size_t)E_ * C_ * H_ / 8;
        f2h_kernel<<<(unsigned)((nx + 255) / 256), 256>>>(x,  xh,  nx);
        f2h_kernel<<<(unsigned)((nw + 255) / 256), 256>>>(w1, w1h, nw);
        f2h_kernel<<<(unsigned)((nw + 255) / 256), 256>>>(w2, w2h, nw);
    }

    gate_kernel<<<(B_ * T_) / 8, 256>>>(x, gw);
    topk_kernel<<<B_ * E_, 512>>>();

    // GEMM1: h = gelu(xin @ w1)   [M=1024, N=4096, K=1024] per (b,e)
    {
        dim3 grid(H_ / 128, CAP / 128, B_ * E_);
        moe_gemm<C_, H_, true, true><<<grid, 256, SMEM>>>(xh, w1h, nullptr);
    }
    // GEMM2: out += (h @ w2) * p  [M=1024, N=1024, K=4096] per (b,e)
    {
        dim3 grid(C_ / 128, CAP / 128, B_ * E_);
        moe_gemm<H_, C_, false, false><<<grid, 256, SMEM>>>(nullptr, w2h, out);
    }
}